// round 3
// baseline (speedup 1.0000x reference)
#include <cuda_runtime.h>
#include <cstdint>

typedef unsigned long long ull;

#define BATCH 4
#define NPTS  8192
#define RT    64           // rows (pred points) per block
#define RPW   8            // rows per warp
#define CG    1024         // cols (gt points) per block
#define NRT   (NPTS/RT)    // 128 row tiles
#define NCG   (NPTS/CG)    // 8  col groups
#define NPASS (CG/64)      // 16 passes (64 cols per pass, 2 per lane)

// Scratch (disjoint writers -> no init, no atomics, deterministic)
__device__ float g_rpart[NCG * BATCH * NPTS];   // [cg][b][n]
__device__ float g_cpart[NRT * BATCH * NPTS];   // [rt][b][m]
__device__ float g_pr[128], g_pc[128];

// ---- packed f32x2 helpers (sm_100+) ----
__device__ __forceinline__ ull pk2(float lo, float hi) {
    ull r; asm("mov.b64 %0, {%1, %2};" : "=l"(r) : "f"(lo), "f"(hi)); return r;
}
__device__ __forceinline__ void upk2(ull v, float& lo, float& hi) {
    asm("mov.b64 {%0, %1}, %2;" : "=f"(lo), "=f"(hi) : "l"(v));
}
__device__ __forceinline__ ull ffma2(ull a, ull b, ull c) {
    ull d; asm("fma.rn.f32x2 %0, %1, %2, %3;" : "=l"(d) : "l"(a), "l"(b), "l"(c)); return d;
}
__device__ __forceinline__ ull fadd2(ull a, ull b) {
    ull d; asm("add.rn.f32x2 %0, %1, %2;" : "=l"(d) : "l"(a), "l"(b)); return d;
}

// ============================================================================
// Warp-owns-rows fused kernel. Block = (cg, rt, b); 8 warps x 32 lanes.
// Warp w owns rows [w*8, w*8+8); lane owns col pair (pass*64 + lane*2) per pass.
// dist = ||p||^2 + ||g||^2 - 2 p.g:
//   s = fma(-2py, gy, fma(-2px, gx, g2));  row-min accumulates s (x2 added once)
//   d = s + x2  -> col-min per lane over the warp's 8 rows, STS once per pass.
// Only 2 barriers per block.
// ============================================================================
__global__ __launch_bounds__(256, 3) void chamfer_tile(const float* __restrict__ pred,
                                                       const float* __restrict__ gt) {
    const int cg = blockIdx.x, rt = blockIdx.y, b = blockIdx.z;
    const int tid = threadIdx.x;
    const int w = tid >> 5, lane = tid & 31;

    __shared__ __align__(16) float s_gx[CG], s_gy[CG], s_g2[CG];
    __shared__ __align__(16) float s_px2[RT], s_py2[RT], s_x2[RT];
    __shared__ __align__(16) float s_colpart[8][CG];

    // Vectorized loads; derived quantities computed inline (both components visible)
    const float2* gt2 = (const float2*)gt + (size_t)b * NPTS + (size_t)cg * CG;
    #pragma unroll
    for (int k = 0; k < CG / 256; k++) {
        int i = tid + k * 256;
        float2 v = gt2[i];
        s_gx[i] = v.x; s_gy[i] = v.y; s_g2[i] = v.x * v.x + v.y * v.y;
    }
    if (tid < RT) {
        float2 p = ((const float2*)pred)[(size_t)b * NPTS + (size_t)rt * RT + tid];
        s_px2[tid] = -2.0f * p.x;
        s_py2[tid] = -2.0f * p.y;
        s_x2[tid]  = p.x * p.x + p.y * p.y;
    }
    __syncthreads();

    // Row constants for this warp's 8 rows (packed broadcasts)
    ull px2p[RPW], py2p[RPW], x2p[RPW];
    float racc[RPW];
    const int r0 = w * RPW;
    #pragma unroll
    for (int r = 0; r < RPW; r++) {
        float a = s_px2[r0 + r]; px2p[r] = pk2(a, a);
        float c = s_py2[r0 + r]; py2p[r] = pk2(c, c);
        float e = s_x2[r0 + r];  x2p[r]  = pk2(e, e);
        racc[r] = 3.4e38f;
    }

    // Main sweep: 16 passes x 8 rows x 2 cols per lane
    #pragma unroll 1
    for (int pass = 0; pass < NPASS; pass++) {
        const int c = pass * 64 + lane * 2;
        ull gxp = *(const ull*)&s_gx[c];
        ull gyp = *(const ull*)&s_gy[c];
        ull g2p = *(const ull*)&s_g2[c];
        float clo = 3.4e38f, chi = 3.4e38f;
        #pragma unroll
        for (int r = 0; r < RPW; r++) {
            ull s = ffma2(px2p[r], gxp, g2p);      // -2px*gx + g2
            s = ffma2(py2p[r], gyp, s);            // += -2py*gy
            float lo, hi; upk2(s, lo, hi);
            racc[r] = fminf(racc[r], fminf(lo, hi));
            ull d = fadd2(s, x2p[r]);              // full distance
            float dlo, dhi; upk2(d, dlo, dhi);
            clo = fminf(clo, dlo);
            chi = fminf(chi, dhi);
        }
        // Exclusive per-warp column partial (no sync needed)
        *(float2*)&s_colpart[w][c] = make_float2(clo, chi);
    }

    // Row mins: warp shuffle reduce (no barrier)
    #pragma unroll
    for (int r = 0; r < RPW; r++) {
        float x2lo, x2hi; upk2(x2p[r], x2lo, x2hi);
        float v = x2lo + racc[r];
        v = fminf(v, __shfl_xor_sync(0xFFFFFFFFu, v, 16));
        v = fminf(v, __shfl_xor_sync(0xFFFFFFFFu, v, 8));
        v = fminf(v, __shfl_xor_sync(0xFFFFFFFFu, v, 4));
        v = fminf(v, __shfl_xor_sync(0xFFFFFFFFu, v, 2));
        v = fminf(v, __shfl_xor_sync(0xFFFFFFFFu, v, 1));
        if (lane == 0)
            g_rpart[((size_t)cg * BATCH + b) * NPTS + (size_t)rt * RT + r0 + r] = v;
    }

    // Column combine across the 8 warps: one barrier, vectorized
    __syncthreads();
    {
        const int c0 = tid * 4;
        float4 m = *(const float4*)&s_colpart[0][c0];
        #pragma unroll
        for (int k = 1; k < 8; k++) {
            float4 v = *(const float4*)&s_colpart[k][c0];
            m.x = fminf(m.x, v.x); m.y = fminf(m.y, v.y);
            m.z = fminf(m.z, v.z); m.w = fminf(m.w, v.w);
        }
        *(float4*)&g_cpart[((size_t)rt * BATCH + b) * NPTS + (size_t)cg * CG + c0] = m;
    }
}

// ============================================================================
// Reduce 1: thread g finishes row entry (8-way) and col entry (128-way, 4
// independent accumulators for MLP), then block-sums both.
// ============================================================================
__global__ __launch_bounds__(256) void chamfer_reduce1() {
    const int t = threadIdx.x;
    const int g = blockIdx.x * 256 + t;   // 0..32767
    const size_t BN = (size_t)BATCH * NPTS;

    float rm = g_rpart[g];
    #pragma unroll
    for (int k = 1; k < NCG; k++) rm = fminf(rm, g_rpart[(size_t)k * BN + g]);

    float a0 = 3.4e38f, a1 = 3.4e38f, a2 = 3.4e38f, a3 = 3.4e38f;
    #pragma unroll 4
    for (int k = 0; k < NRT; k += 4) {
        a0 = fminf(a0, g_cpart[(size_t)(k + 0) * BN + g]);
        a1 = fminf(a1, g_cpart[(size_t)(k + 1) * BN + g]);
        a2 = fminf(a2, g_cpart[(size_t)(k + 2) * BN + g]);
        a3 = fminf(a3, g_cpart[(size_t)(k + 3) * BN + g]);
    }
    float cm = fminf(fminf(a0, a1), fminf(a2, a3));

    __shared__ float sr[256], sc[256];
    sr[t] = rm; sc[t] = cm;
    __syncthreads();
    for (int off = 128; off > 0; off >>= 1) {
        if (t < off) { sr[t] += sr[t + off]; sc[t] += sc[t + off]; }
        __syncthreads();
    }
    if (t == 0) { g_pr[blockIdx.x] = sr[0]; g_pc[blockIdx.x] = sc[0]; }
}

// ============================================================================
// Reduce 2: single block, fixed order -> deterministic.
// ============================================================================
__global__ void chamfer_reduce2(float* __restrict__ out) {
    __shared__ float sr[128], sc[128];
    const int t = threadIdx.x;   // 128 threads
    sr[t] = g_pr[t]; sc[t] = g_pc[t];
    __syncthreads();
    for (int off = 64; off > 0; off >>= 1) {
        if (t < off) { sr[t] += sr[t + off]; sc[t] += sc[t + off]; }
        __syncthreads();
    }
    if (t == 0) out[0] = (sr[0] + sc[0]) * (1.0f / (float)(BATCH * NPTS));
}

extern "C" void kernel_launch(void* const* d_in, const int* in_sizes, int n_in,
                              void* d_out, int out_size) {
    const float* pred = (const float*)d_in[0];
    const float* gt   = (const float*)d_in[1];

    dim3 grid(NCG, NRT, BATCH);          // 8 x 128 x 4 = 4096 blocks
    chamfer_tile<<<grid, 256>>>(pred, gt);
    chamfer_reduce1<<<128, 256>>>();
    chamfer_reduce2<<<1, 128>>>((float*)d_out);
}